// round 2
// baseline (speedup 1.0000x reference)
#include <cuda_runtime.h>
#include <math.h>

#define TB 16
#define TS 256

// ---------------- f32x2 packed helpers ----------------
__device__ __forceinline__ unsigned long long pk2(float lo, float hi) {
    unsigned long long r;
    asm("mov.b64 %0, {%1,%2};" : "=l"(r) : "f"(lo), "f"(hi));
    return r;
}
__device__ __forceinline__ void upk2(float& lo, float& hi, unsigned long long v) {
    asm("mov.b64 {%0,%1}, %2;" : "=f"(lo), "=f"(hi) : "l"(v));
}
#define FMA2(d, a, b, c) asm("fma.rn.f32x2 %0, %1, %2, %3;" : "=l"(d) : "l"(a), "l"(b), "l"(c))
#define MUL2(d, a, b)    asm("mul.rn.f32x2 %0, %1, %2;"     : "=l"(d) : "l"(a), "l"(b))
#define ADD2(d, a, b)    asm("add.rn.f32x2 %0, %1, %2;"     : "=l"(d) : "l"(a), "l"(b))

// ---------------- device scratch ----------------
__device__ float g_h1[8*16*64*64];
__device__ float g_part[128*32];
__device__ float g_Wupd[2304];              // [co][ci][pos]
__device__ float g_Wtau[256];               // [co][ci]
__device__ float g_T9[9*33*18];             // [pos][code(33:32=zero)][c] stride-18
__device__ float g_Acb[32*18];              // beta*code
__device__ float g_OMB[32*18];              // 1-beta
__device__ float g_cbsq[32];
__device__ float g_declut[32];
__device__ unsigned char g_idxA[TB*TS*TS];
__device__ unsigned char g_idxB[TB*TS*TS];

// ---------------- encoder conv1 ----------------
__global__ __launch_bounds__(256) void k_enc1(const float* __restrict__ din,
                                              const float* __restrict__ dmo,
                                              const float* __restrict__ w1,
                                              const float* __restrict__ b1)
{
    __shared__ float sw[288];
    __shared__ float sb[16];
    int t = threadIdx.x;
    for (int i = t; i < 288; i += 256) sw[i] = w1[i];
    if (t < 16) sb[t] = b1[t];
    __syncthreads();
    int idx = blockIdx.x * 256 + t;
    int b = idx >> 12, p = idx & 4095, y = p >> 6, x = p & 63;
    const float* i0 = din + b * 4096;
    const float* i1 = dmo + b * 4096;
    float acc[16];
#pragma unroll
    for (int c = 0; c < 16; c++) acc[c] = sb[c];
#pragma unroll
    for (int ky = 0; ky < 3; ky++) {
        int yy = y + ky - 1;
        if ((unsigned)yy >= 64u) continue;
#pragma unroll
        for (int kx = 0; kx < 3; kx++) {
            int xx = x + kx - 1;
            if ((unsigned)xx >= 64u) continue;
            float v0 = i0[yy*64+xx], v1 = i1[yy*64+xx];
            int pos = ky*3+kx;
#pragma unroll
            for (int c = 0; c < 16; c++)
                acc[c] = fmaf(sw[c*18+pos], v0, fmaf(sw[c*18+9+pos], v1, acc[c]));
        }
    }
#pragma unroll
    for (int c = 0; c < 16; c++)
        g_h1[((b*16+c) << 12) + p] = fmaxf(acc[c], 0.f);
}

// ---------------- encoder conv2 + relu + spatial sum ----------------
__global__ __launch_bounds__(256) void k_enc2(const float* __restrict__ w2,
                                              const float* __restrict__ b2)
{
    __shared__ float sh[16][6][66];
    __shared__ float sw[32][145];
    __shared__ float spart[8][32];
    int tx = threadIdx.x, ty = threadIdx.y;
    int t = ty * 32 + tx;
    int band = blockIdx.x, b = blockIdx.y;
    float* swf = &sw[0][0];
    for (int i = t; i < 4608; i += 256) { int oc = i/144, j = i%144; swf[oc*145+j] = w2[i]; }
    int r0 = band * 4;
    for (int i = t; i < 16*6*66; i += 256) {
        int ci = i / 396; int rem = i % 396; int r = rem / 66; int xx = rem % 66;
        int gy = r0 + r - 1; int gx = xx - 1;
        float v = 0.f;
        if ((unsigned)gy < 64u && (unsigned)gx < 64u)
            v = g_h1[((b*16+ci) << 12) + gy*64 + gx];
        sh[ci][r][xx] = v;
    }
    __syncthreads();
    int oc = tx;
    float bias = b2[oc];
    float tsum = 0.f;
    for (int p = ty; p < 256; p += 8) {
        int r = p >> 6; int x = p & 63;
        float acc = bias;
#pragma unroll
        for (int ky = 0; ky < 3; ky++) {
#pragma unroll
            for (int kx = 0; kx < 3; kx++) {
                int pos = ky*3+kx;
#pragma unroll
                for (int ci = 0; ci < 16; ci++)
                    acc = fmaf(sh[ci][r+ky][x+kx], swf[oc*145 + ci*9 + pos], acc);
            }
        }
        tsum += fmaxf(acc, 0.f);
    }
    spart[ty][oc] = tsum;
    __syncthreads();
    if (ty == 0) {
        float s = 0.f;
#pragma unroll
        for (int k = 0; k < 8; k++) s += spart[k][oc];
        g_part[(b*16+band)*32 + oc] = s;
    }
}

// ---------------- tiny stage: te, hypernets, tables ----------------
__global__ __launch_bounds__(256) void k_small(
    const float* __restrict__ enc_lw, const float* __restrict__ enc_lb,
    const float* __restrict__ gu_w1, const float* __restrict__ gu_b1,
    const float* __restrict__ gu_w2, const float* __restrict__ gu_b2,
    const float* __restrict__ gt_w1, const float* __restrict__ gt_b1,
    const float* __restrict__ gt_w2, const float* __restrict__ gt_b2,
    const float* __restrict__ cb, const float* __restrict__ dec_w,
    const float* __restrict__ dec_b)
{
    __shared__ float s_hbar[32];
    __shared__ float s_te[64];
    __shared__ float s_hu[128];
    __shared__ float s_ht[64];
    __shared__ float s_cb[512];
    int t = threadIdx.x;
    if (t < 32) {
        float s = 0.f;
        for (int i = 0; i < 128; i++) s += g_part[i*32 + t];
        s_hbar[t] = s * (1.f/(8.f*4096.f));
    }
    for (int i = t; i < 512; i += 256) s_cb[i] = cb[i];
    __syncthreads();
    if (t < 64) {
        float a = enc_lb[t];
        for (int f = 0; f < 32; f++) a = fmaf(enc_lw[t*32+f], s_hbar[f], a);
        s_te[t] = a;
    }
    __syncthreads();
    if (t < 128) {
        float a = gu_b1[t];
        for (int e = 0; e < 64; e++) a = fmaf(gu_w1[t*64+e], s_te[e], a);
        s_hu[t] = fmaxf(a, 0.f);
    } else if (t < 192) {
        int i = t - 128;
        float a = gt_b1[i];
        for (int e = 0; e < 64; e++) a = fmaf(gt_w1[i*64+e], s_te[e], a);
        s_ht[i] = fmaxf(a, 0.f);
    }
    __syncthreads();
    for (int o = t; o < 2304; o += 256) {
        float a = gu_b2[o];
        for (int i = 0; i < 128; i++) a = fmaf(gu_w2[o*128+i], s_hu[i], a);
        g_Wupd[o] = a;
    }
    for (int o = t; o < 256; o += 256) {
        float a = gt_b2[o];
        for (int i = 0; i < 64; i++) a = fmaf(gt_w2[o*64+i], s_ht[i], a);
        g_Wtau[o] = a;
    }
    __syncthreads();
    for (int o = t; o < 9*33*16; o += 256) {
        int pos = o / 528, rem = o % 528, k = rem >> 4, c = rem & 15;
        float v = 0.f;
        if (k < 32) {
            for (int ci = 0; ci < 16; ci++)
                v = fmaf(g_Wupd[(c*16+ci)*9 + pos], s_cb[k*16+ci], v);
        }
        g_T9[(pos*33+k)*18 + c] = v;
    }
    for (int o = t; o < 512; o += 256) {
        int k = o >> 4, c = o & 15;
        float a = 0.f;
        for (int ci = 0; ci < 16; ci++) a = fmaf(g_Wtau[c*16+ci], s_cb[k*16+ci], a);
        float beta = 1.f / (1.f + __expf(-a));
        g_Acb[k*18+c] = beta * s_cb[k*16+c];
        g_OMB[k*18+c] = 1.f - beta;
    }
    if (t < 32) {
        float sq = 0.f, dv = dec_b[0];
        for (int c = 0; c < 16; c++) {
            float cc = s_cb[t*16+c];
            sq = fmaf(cc, cc, sq);
            dv = fmaf(dec_w[c], cc, dv);
        }
        g_cbsq[t] = sq;
        g_declut[t] = 1.f / (1.f + __expf(-dv));
    }
}

// ---------------- fused stem + step 1 (conv + tau + mix + VQ) ----------------
__global__ __launch_bounds__(256) void k_step1f(const float* __restrict__ tin,
                                                const float* __restrict__ stw,
                                                const float* __restrict__ stb,
                                                const float* __restrict__ cb)
{
    __shared__ __align__(16) float4 s_t[4*10*34];   // [chunk q][row][col] = stem state
    __shared__ __align__(16) float sin_[12*36];     // raw input tile with halo 2
    __shared__ __align__(16) float s_sw[144];       // stem w [pos][co]
    __shared__ __align__(16) float s_sb[16];
    __shared__ __align__(16) float s_W[2304];       // [pos][ci][co]
    __shared__ __align__(16) float s_Wt[256];       // [ci][co]
    __shared__ __align__(16) float s_cb[512];
    __shared__ float s_cq[32];
    int tx = threadIdx.x, ty = threadIdx.y, t = ty*32+tx;
    for (int i = t; i < 144; i += 256) { int co = i/9, pos = i%9; s_sw[pos*16+co] = stw[i]; }
    if (t < 16) s_sb[t] = stb[t];
    for (int i = t; i < 2304; i += 256) {
        int co = i & 15, ci = (i >> 4) & 15, pos = i >> 8;
        s_W[i] = g_Wupd[(co*16+ci)*9 + pos];
    }
    for (int i = t; i < 256; i += 256) { int co = i & 15, ci = i >> 4; s_Wt[i] = g_Wtau[co*16+ci]; }
    for (int i = t; i < 512; i += 256) s_cb[i] = cb[i];
    if (t < 32) s_cq[t] = g_cbsq[t];
    int X0 = blockIdx.x*32, Y0 = blockIdx.y*8, b = blockIdx.z;
    const float* img = tin + (size_t)b*65536;
    for (int i = t; i < 432; i += 256) {
        int rr = i/36, cc = i%36;
        int gy = Y0-2+rr, gx = X0-2+cc;
        float v = 0.f;
        if ((unsigned)gy < 256u && (unsigned)gx < 256u) v = img[gy*256+gx];
        sin_[rr*36+cc] = v;
    }
    __syncthreads();
    // stem over 10x34 halo region (zero outside image)
    const unsigned long long* sw2base = (const unsigned long long*)s_sw;
    unsigned long long sb2[8];
#pragma unroll
    for (int m = 0; m < 8; m++) sb2[m] = ((const unsigned long long*)s_sb)[m];
    for (int i = t; i < 340; i += 256) {
        int r = i/34, c = i%34;
        int gy = Y0+r-1, gx = X0+c-1;
        float4 o0, o1, o2, o3;
        if ((unsigned)gy < 256u && (unsigned)gx < 256u) {
            unsigned long long a2[8];
#pragma unroll
            for (int m = 0; m < 8; m++) a2[m] = sb2[m];
#pragma unroll
            for (int pos = 0; pos < 9; pos++) {
                float v = sin_[(r + pos/3)*36 + (c + pos%3)];
                unsigned long long vv = pk2(v, v);
                const unsigned long long* wr = sw2base + pos*8;
#pragma unroll
                for (int m = 0; m < 8; m++) FMA2(a2[m], wr[m], vv, a2[m]);
            }
            float s[16];
#pragma unroll
            for (int m = 0; m < 8; m++) {
                float lo, hi; upk2(lo, hi, a2[m]);
                s[2*m] = fmaxf(lo, 0.f); s[2*m+1] = fmaxf(hi, 0.f);
            }
            o0 = make_float4(s[0],s[1],s[2],s[3]);
            o1 = make_float4(s[4],s[5],s[6],s[7]);
            o2 = make_float4(s[8],s[9],s[10],s[11]);
            o3 = make_float4(s[12],s[13],s[14],s[15]);
        } else {
            o0 = make_float4(0,0,0,0); o1 = o0; o2 = o0; o3 = o0;
        }
        s_t[(0*10+r)*34+c] = o0;
        s_t[(1*10+r)*34+c] = o1;
        s_t[(2*10+r)*34+c] = o2;
        s_t[(3*10+r)*34+c] = o3;
    }
    __syncthreads();
    // 3x3 conv (packed f32x2)
    unsigned long long acc2[8];
#pragma unroll
    for (int m = 0; m < 8; m++) acc2[m] = 0ull;
    const unsigned long long* W2 = (const unsigned long long*)s_W;
#pragma unroll
    for (int pos = 0; pos < 9; pos++) {
        int rr = ty + pos/3, cc = tx + pos%3;
#pragma unroll
        for (int q = 0; q < 4; q++) {
            float4 v = s_t[(q*10+rr)*34+cc];
            float vs[4] = {v.x, v.y, v.z, v.w};
#pragma unroll
            for (int u = 0; u < 4; u++) {
                unsigned long long ss = pk2(vs[u], vs[u]);
                const unsigned long long* wr = W2 + (pos*16 + q*4 + u)*8;
#pragma unroll
                for (int m = 0; m < 8; m++) FMA2(acc2[m], wr[m], ss, acc2[m]);
            }
        }
    }
    // center state
    float zc[16];
#pragma unroll
    for (int q = 0; q < 4; q++) {
        float4 v = s_t[(q*10 + ty+1)*34 + tx+1];
        zc[q*4+0] = v.x; zc[q*4+1] = v.y; zc[q*4+2] = v.z; zc[q*4+3] = v.w;
    }
    // tau conv1x1 (packed)
    unsigned long long ta2[8];
#pragma unroll
    for (int m = 0; m < 8; m++) ta2[m] = 0ull;
    const unsigned long long* Wt2 = (const unsigned long long*)s_Wt;
#pragma unroll
    for (int ci = 0; ci < 16; ci++) {
        unsigned long long ss = pk2(zc[ci], zc[ci]);
        const unsigned long long* wr = Wt2 + ci*8;
#pragma unroll
        for (int m = 0; m < 8; m++) FMA2(ta2[m], wr[m], ss, ta2[m]);
    }
    float z[16];
#pragma unroll
    for (int m = 0; m < 8; m++) {
        float al, ah, tl, th;
        upk2(al, ah, acc2[m]);
        upk2(tl, th, ta2[m]);
        float b0 = 1.f / (1.f + __expf(-tl));
        float b1 = 1.f / (1.f + __expf(-th));
        float d0 = fmaxf(al, 0.f), d1 = fmaxf(ah, 0.f);
        z[2*m]   = fmaf(b0, zc[2*m]   - d0, d0);
        z[2*m+1] = fmaf(b1, zc[2*m+1] - d1, d1);
    }
    // VQ argmin (packed)
    unsigned long long z2[8];
#pragma unroll
    for (int m = 0; m < 8; m++) z2[m] = pk2(z[2*m], z[2*m+1]);
    const unsigned long long* C2 = (const unsigned long long*)s_cb;
    float best = 3.4e38f; int bi = 0;
#pragma unroll
    for (int k = 0; k < 32; k++) {
        const unsigned long long* c2 = C2 + k*8;
        unsigned long long d2;
        MUL2(d2, c2[0], z2[0]);
#pragma unroll
        for (int m = 1; m < 8; m++) FMA2(d2, c2[m], z2[m], d2);
        float lo, hi; upk2(lo, hi, d2);
        float d = s_cq[k] - 2.f*(lo + hi);
        if (d < best) { best = d; bi = k; }
    }
    g_idxA[(b << 16) + (Y0+ty)*256 + (X0+tx)] = (unsigned char)bi;
}

// ---------------- quantized step (iterations 2..5), final fuses decoder ----------------
__global__ __launch_bounds__(256) void k_stepq(int iter, int srcsel, int final_,
                                               const float* __restrict__ cb,
                                               const int* __restrict__ nsp,
                                               float* __restrict__ out)
{
    int ns = *nsp;
    const unsigned char* src = srcsel ? g_idxB : g_idxA;
    unsigned char* dst = srcsel ? g_idxA : g_idxB;
    int tx = threadIdx.x, ty = threadIdx.y, t = ty*32+tx;
    int X0 = blockIdx.x*32, Y0 = blockIdx.y*8, b = blockIdx.z;
    int gp = (b << 16) + (Y0+ty)*256 + (X0+tx);
    if (iter > ns) {                        // uniform branch
        unsigned char v = src[gp];
        dst[gp] = v;
        if (final_) out[gp] = g_declut[v];
        return;
    }

    __shared__ __align__(16) float sT[9*33*18];
    __shared__ __align__(16) float sA[32*18];
    __shared__ __align__(16) float sO[32*18];
    __shared__ __align__(16) float s_cb[512];
    __shared__ float s_cq[32];
    __shared__ float s_lut[32];
    __shared__ unsigned char sj[10*34];
    for (int i = t; i < 9*33*18; i += 256) sT[i] = g_T9[i];
    for (int i = t; i < 576; i += 256) { sA[i] = g_Acb[i]; sO[i] = g_OMB[i]; }
    for (int i = t; i < 512; i += 256) s_cb[i] = cb[i];
    if (t < 32) { s_cq[t] = g_cbsq[t]; s_lut[t] = g_declut[t]; }
    for (int i = t; i < 340; i += 256) {
        int r = i/34, c = i%34;
        int gy = Y0+r-1, gx = X0+c-1;
        unsigned char v = 32;
        if ((unsigned)gy < 256u && (unsigned)gx < 256u)
            v = src[(b << 16) + gy*256 + gx];
        sj[r*34+c] = v;
    }
    __syncthreads();
    unsigned long long acc2[8];
#pragma unroll
    for (int m = 0; m < 8; m++) acc2[m] = 0ull;
#pragma unroll
    for (int pos = 0; pos < 9; pos++) {
        int j = sj[(ty + pos/3)*34 + tx + pos%3];
        const unsigned long long* T2 = (const unsigned long long*)&sT[(pos*33 + j)*18];
#pragma unroll
        for (int m = 0; m < 8; m++) {
            unsigned long long tv = T2[m];
            ADD2(acc2[m], acc2[m], tv);
        }
    }
    int j0 = sj[(ty+1)*34 + tx+1];
    const float* A = &sA[j0*18];
    const float* O = &sO[j0*18];
    float z[16];
#pragma unroll
    for (int m = 0; m < 8; m++) {
        float lo, hi; upk2(lo, hi, acc2[m]);
        z[2*m]   = fmaf(O[2*m],   fmaxf(lo, 0.f), A[2*m]);
        z[2*m+1] = fmaf(O[2*m+1], fmaxf(hi, 0.f), A[2*m+1]);
    }
    unsigned long long z2[8];
#pragma unroll
    for (int m = 0; m < 8; m++) z2[m] = pk2(z[2*m], z[2*m+1]);
    const unsigned long long* C2 = (const unsigned long long*)s_cb;
    float best = 3.4e38f; int bi = 0;
#pragma unroll
    for (int k = 0; k < 32; k++) {
        const unsigned long long* c2 = C2 + k*8;
        unsigned long long d2;
        MUL2(d2, c2[0], z2[0]);
#pragma unroll
        for (int m = 1; m < 8; m++) FMA2(d2, c2[m], z2[m], d2);
        float lo, hi; upk2(lo, hi, d2);
        float d = s_cq[k] - 2.f*(lo + hi);
        if (d < best) { best = d; bi = k; }
    }
    dst[gp] = (unsigned char)bi;
    if (final_) out[gp] = s_lut[bi];
}

extern "C" void kernel_launch(void* const* d_in, const int* in_sizes, int n_in,
                              void* d_out, int out_size)
{
    const float* demo_in  = (const float*)d_in[0];
    const float* demo_out = (const float*)d_in[1];
    const float* test_in  = (const float*)d_in[2];
    const float* enc_w1   = (const float*)d_in[3];
    const float* enc_b1   = (const float*)d_in[4];
    const float* enc_w2   = (const float*)d_in[5];
    const float* enc_b2   = (const float*)d_in[6];
    const float* enc_lw   = (const float*)d_in[7];
    const float* enc_lb   = (const float*)d_in[8];
    const float* gu_w1    = (const float*)d_in[9];
    const float* gu_b1    = (const float*)d_in[10];
    const float* gu_w2    = (const float*)d_in[11];
    const float* gu_b2    = (const float*)d_in[12];
    const float* gt_w1    = (const float*)d_in[13];
    const float* gt_b1    = (const float*)d_in[14];
    const float* gt_w2    = (const float*)d_in[15];
    const float* gt_b2    = (const float*)d_in[16];
    const float* stem_w   = (const float*)d_in[17];
    const float* stem_b   = (const float*)d_in[18];
    const float* codebook = (const float*)d_in[19];
    const float* dec_w    = (const float*)d_in[20];
    const float* dec_b    = (const float*)d_in[21];
    const int*   n_steps  = (const int*)d_in[22];

    k_enc1<<<128, 256>>>(demo_in, demo_out, enc_w1, enc_b1);
    k_enc2<<<dim3(16,8), dim3(32,8)>>>(enc_w2, enc_b2);
    k_small<<<1, 256>>>(enc_lw, enc_lb, gu_w1, gu_b1, gu_w2, gu_b2,
                        gt_w1, gt_b1, gt_w2, gt_b2, codebook, dec_w, dec_b);
    dim3 grid(8, 32, TB), blk(32, 8);
    k_step1f<<<grid, blk>>>(test_in, stem_w, stem_b, codebook);
    float* out = (float*)d_out;
    k_stepq<<<grid, blk>>>(2, 0, 0, codebook, n_steps, out);
    k_stepq<<<grid, blk>>>(3, 1, 0, codebook, n_steps, out);
    k_stepq<<<grid, blk>>>(4, 0, 0, codebook, n_steps, out);
    k_stepq<<<grid, blk>>>(5, 1, 1, codebook, n_steps, out);
}